// round 1
// baseline (speedup 1.0000x reference)
#include <cuda_runtime.h>
#include <math.h>

#define B_TOT  16384
#define M_MEM  50
#define D_DIM  64
#define PAD    68   // memS row stride in floats (68 = 4*17: float4-aligned, conflict-free LDS.128)

__global__ __launch_bounds__(64, 9)
void agree_fused_kernel(
    const int* __restrict__ group_inputs,
    const int* __restrict__ item_inputs,
    const int* __restrict__ member_ids,
    const int* __restrict__ member_lengths,
    const float* __restrict__ user_table,
    const float* __restrict__ item_table,
    const float* __restrict__ group_table,
    const float* __restrict__ att_w1,   // [128,16]
    const float* __restrict__ att_b1,   // [16]
    const float* __restrict__ att_w2,   // [16]
    const float* __restrict__ att_b2,   // [1]
    const float* __restrict__ pred_w1,  // [192,8]
    const float* __restrict__ pred_b1,  // [8]
    const float* __restrict__ pred_w2,  // [8]
    const float* __restrict__ pred_b2,  // [1]
    float* __restrict__ out)            // [B]
{
    __shared__ float memS[M_MEM * PAD];     // 13600 B
    __shared__ float w1S[D_DIM * 16];       // 4096 B  (member half of att_w1)
    __shared__ float predW[192 * 8];        // 6144 B
    __shared__ float itemS[D_DIM];
    __shared__ float groupS[D_DIM];
    __shared__ float gS[D_DIM];
    __shared__ float ctbS[16];
    __shared__ float w2S[16];
    __shared__ float scoreS[M_MEM];
    __shared__ float wtS[M_MEM];
    __shared__ int   idS[M_MEM];

    const int b   = blockIdx.x;
    const int tid = threadIdx.x;

    const int item_idx = item_inputs[b];
    const int grp_idx  = group_inputs[b];
    const int len      = member_lengths[b];

    if (tid < M_MEM) idS[tid] = member_ids[b * M_MEM + tid];
    itemS[tid]  = item_table[item_idx * D_DIM + tid];
    groupS[tid] = group_table[grp_idx * D_DIM + tid];

    // member half of att_w1 (rows 0..63) -> shared, verbatim (row-major [d][j])
    {
        float4* dstA = (float4*)w1S;
        const float4* srcA = (const float4*)att_w1;
        #pragma unroll
        for (int i = 0; i < 4; i++) dstA[tid + i * 64] = srcA[tid + i * 64];
    }
    // pred_w1 -> shared (1536 floats = 384 float4)
    {
        float4* dstP = (float4*)predW;
        const float4* srcP = (const float4*)pred_w1;
        #pragma unroll
        for (int i = 0; i < 6; i++) dstP[tid + i * 64] = srcP[tid + i * 64];
    }
    if (tid < 16) w2S[tid] = att_w2[tid];
    __syncthreads();   // idS, itemS ready

    // coalesced gather of 50 member rows (16 float4 per row)
    for (int i = tid; i < M_MEM * 16; i += 64) {
        int r = i >> 4, c = i & 15;
        float4 v = ((const float4*)(user_table + (size_t)idS[r] * D_DIM))[c];
        *((float4*)(memS + r * PAD + c * 4)) = v;
    }
    // item contribution to attention hidden: ctb[j] = b1[j] + sum_d item[d]*W1[64+d][j]
    if (tid < 16) {
        float a = att_b1[tid];
        #pragma unroll 8
        for (int d = 0; d < D_DIM; d++)
            a += itemS[d] * att_w1[(D_DIM + d) * 16 + tid];
        ctbS[tid] = a;
    }
    __syncthreads();

    // ---- attention scores: one member per thread ----
    if (tid < M_MEM) {
        float acc[16];
        #pragma unroll
        for (int j = 0; j < 16; j++) acc[j] = ctbS[j];

        const float4* mrow = (const float4*)(memS + tid * PAD);
        const float4* w14  = (const float4*)w1S;
        #pragma unroll 4
        for (int dq = 0; dq < 16; dq++) {
            float4 mv = mrow[dq];
            #pragma unroll
            for (int r = 0; r < 4; r++) {
                float m = (r == 0) ? mv.x : (r == 1) ? mv.y : (r == 2) ? mv.z : mv.w;
                int d = dq * 4 + r;
                float4 wa = w14[d * 4 + 0];
                float4 wb = w14[d * 4 + 1];
                float4 wc = w14[d * 4 + 2];
                float4 wd = w14[d * 4 + 3];
                acc[0]  += m * wa.x; acc[1]  += m * wa.y; acc[2]  += m * wa.z; acc[3]  += m * wa.w;
                acc[4]  += m * wb.x; acc[5]  += m * wb.y; acc[6]  += m * wb.z; acc[7]  += m * wb.w;
                acc[8]  += m * wc.x; acc[9]  += m * wc.y; acc[10] += m * wc.z; acc[11] += m * wc.w;
                acc[12] += m * wd.x; acc[13] += m * wd.y; acc[14] += m * wd.z; acc[15] += m * wd.w;
            }
        }
        float s = att_b2[0];
        #pragma unroll
        for (int j = 0; j < 16; j++) s += fmaxf(acc[j], 0.0f) * w2S[j];
        scoreS[tid] = (tid <= len) ? s : -INFINITY;
    }
    __syncthreads();

    // ---- softmax over 50 scores (warp 0) ----
    if (tid < 32) {
        float v1 = scoreS[tid];                       // tid < 32 < 50 always valid slot
        float v2 = (tid + 32 < M_MEM) ? scoreS[tid + 32] : -INFINITY;
        float mx = fmaxf(v1, v2);
        #pragma unroll
        for (int o = 16; o > 0; o >>= 1)
            mx = fmaxf(mx, __shfl_xor_sync(0xffffffffu, mx, o));
        float e1 = __expf(v1 - mx);                   // exp(-inf)=0 handles mask
        float e2 = (tid + 32 < M_MEM) ? __expf(v2 - mx) : 0.0f;
        float sm = e1 + e2;
        #pragma unroll
        for (int o = 16; o > 0; o >>= 1)
            sm += __shfl_xor_sync(0xffffffffu, sm, o);
        float inv = __frcp_rn(sm);
        wtS[tid] = e1 * inv;
        if (tid + 32 < M_MEM) wtS[tid + 32] = e2 * inv;
    }
    __syncthreads();

    // ---- weighted member sum + group embedding: thread = dim ----
    {
        float g = groupS[tid];
        #pragma unroll 10
        for (int m = 0; m < M_MEM; m++)
            g += wtS[m] * memS[m * PAD + tid];
        gS[tid] = g;
    }
    __syncthreads();

    // ---- predict MLP: new_e = [g*item, g, item] (192) -> 8 -> 1 ----
    if (tid < 8) {
        float a = pred_b1[tid];
        #pragma unroll 8
        for (int k = 0; k < D_DIM; k++)
            a += (gS[k] * itemS[k]) * predW[k * 8 + tid];
        #pragma unroll 8
        for (int k = 0; k < D_DIM; k++)
            a += gS[k] * predW[(D_DIM + k) * 8 + tid];
        #pragma unroll 8
        for (int k = 0; k < D_DIM; k++)
            a += itemS[k] * predW[(2 * D_DIM + k) * 8 + tid];
        float part = fmaxf(a, 0.0f) * pred_w2[tid];
        #pragma unroll
        for (int o = 4; o > 0; o >>= 1)
            part += __shfl_xor_sync(0xffu, part, o);
        if (tid == 0) {
            float z = part + pred_b2[0];
            out[b] = 1.0f / (1.0f + __expf(-z));
        }
    }
}

extern "C" void kernel_launch(void* const* d_in, const int* in_sizes, int n_in,
                              void* d_out, int out_size)
{
    const int*   group_inputs   = (const int*)  d_in[0];
    const int*   item_inputs    = (const int*)  d_in[1];
    const int*   member_ids     = (const int*)  d_in[2];
    const int*   member_lengths = (const int*)  d_in[3];
    const float* user_table     = (const float*)d_in[4];
    const float* item_table     = (const float*)d_in[5];
    const float* group_table    = (const float*)d_in[6];
    const float* att_w1         = (const float*)d_in[7];
    const float* att_b1         = (const float*)d_in[8];
    const float* att_w2         = (const float*)d_in[9];
    const float* att_b2         = (const float*)d_in[10];
    const float* pred_w1        = (const float*)d_in[11];
    const float* pred_b1        = (const float*)d_in[12];
    const float* pred_w2        = (const float*)d_in[13];
    const float* pred_b2        = (const float*)d_in[14];
    float* out = (float*)d_out;

    int B = in_sizes[0];
    agree_fused_kernel<<<B, 64>>>(
        group_inputs, item_inputs, member_ids, member_lengths,
        user_table, item_table, group_table,
        att_w1, att_b1, att_w2, att_b2,
        pred_w1, pred_b1, pred_w2, pred_b2, out);
}

// round 2
// speedup vs baseline: 1.3114x; 1.3114x over previous
#include <cuda_runtime.h>
#include <math.h>
#include <stdint.h>

#define M_MEM  50
#define D_DIM  64
#define PAD    68   // memS row stride in floats: float4-aligned, conflict-free LDS.128

__global__ __launch_bounds__(128, 5)
void agree_fused_kernel(
    const int* __restrict__ group_inputs,
    const int* __restrict__ item_inputs,
    const int* __restrict__ member_ids,
    const int* __restrict__ member_lengths,
    const float* __restrict__ user_table,
    const float* __restrict__ item_table,
    const float* __restrict__ group_table,
    const float* __restrict__ att_w1,   // [128,16]
    const float* __restrict__ att_b1,   // [16]
    const float* __restrict__ att_w2,   // [16]
    const float* __restrict__ att_b2,   // [1]
    const float* __restrict__ pred_w1,  // [192,8]
    const float* __restrict__ pred_b1,  // [8]
    const float* __restrict__ pred_w2,  // [8]
    const float* __restrict__ pred_b2,  // [1]
    float* __restrict__ out,            // [B]
    int Btot)
{
    __shared__ float memS[2][M_MEM * PAD];          // 27200 B
    __shared__ float w1S[128 * 16];                 // 8192 B (full att_w1)
    __shared__ float predW[192 * 8];                // 6144 B
    __shared__ float itemS[2][D_DIM];
    __shared__ float groupS[2][D_DIM];
    __shared__ float gS[2][D_DIM];
    __shared__ unsigned long long ctbS2[2][8];      // packed f32x2 ctb
    __shared__ float w2S[16];
    __shared__ float scoreS[2][M_MEM];
    __shared__ float wtS[2][M_MEM];
    __shared__ int   idS[2][M_MEM];

    const int tid  = threadIdx.x;
    const int half = tid >> 6;          // which batch row in this block
    const int lt   = tid & 63;          // lane within row-group
    const int b    = blockIdx.x * 2 + half;
    const bool valid = (b < Btot);
    const int bc   = valid ? b : 0;     // clamped for safe loads

    const int item_idx = item_inputs[bc];
    const int grp_idx  = group_inputs[bc];
    const int len      = member_lengths[bc];

    if (lt < M_MEM) idS[half][lt] = member_ids[bc * M_MEM + lt];
    itemS[half][lt]  = item_table[item_idx * D_DIM + lt];
    groupS[half][lt] = group_table[grp_idx * D_DIM + lt];

    // stage full att_w1 (512 float4) and pred_w1 (384 float4)
    {
        float4* dstA = (float4*)w1S;
        const float4* srcA = (const float4*)att_w1;
        #pragma unroll
        for (int i = 0; i < 4; i++) dstA[tid + i * 128] = srcA[tid + i * 128];
        float4* dstP = (float4*)predW;
        const float4* srcP = (const float4*)pred_w1;
        #pragma unroll
        for (int i = 0; i < 3; i++) dstP[tid + i * 128] = srcP[tid + i * 128];
    }
    if (tid < 16) w2S[tid] = att_w2[tid];
    __syncthreads();   // idS, itemS, w1S ready

    // coalesced gather of 50 member rows per half (16 float4/row)
    for (int i = lt; i < M_MEM * 16; i += 64) {
        int r = i >> 4, c = i & 15;
        float4 v = ((const float4*)(user_table + (size_t)idS[half][r] * D_DIM))[c];
        *((float4*)(memS[half] + r * PAD + c * 4)) = v;
    }
    // ctb[j] = b1[j] + sum_d item[d]*W1[64+d][j]  (16 threads per half)
    if (lt < 16) {
        float a = att_b1[lt];
        #pragma unroll 8
        for (int d = 0; d < D_DIM; d++)
            a += itemS[half][d] * w1S[(D_DIM + d) * 16 + lt];
        ((float*)ctbS2[half])[lt] = a;
    }
    __syncthreads();

    // ---- attention scores: one member per thread, packed f32x2 math ----
    if (lt < M_MEM) {
        unsigned long long acc[8];
        #pragma unroll
        for (int j = 0; j < 8; j++) acc[j] = ctbS2[half][j];

        const float4* mrow = (const float4*)(memS[half] + lt * PAD);
        const uint32_t w1base = (uint32_t)__cvta_generic_to_shared(w1S);

        #pragma unroll 4
        for (int dq = 0; dq < 16; dq++) {
            float4 mv = mrow[dq];
            #pragma unroll
            for (int r = 0; r < 4; r++) {
                float m = (r == 0) ? mv.x : (r == 1) ? mv.y : (r == 2) ? mv.z : mv.w;
                unsigned long long mm;
                uint32_t mu = __float_as_uint(m);
                asm("mov.b64 %0, {%1, %1};" : "=l"(mm) : "r"(mu));
                uint32_t wa = w1base + (dq * 4 + r) * 64;  // 16 floats per d
                unsigned long long w0, w1, w2, w3, w4, w5, w6, w7;
                asm("ld.shared.v2.u64 {%0,%1}, [%2];"    : "=l"(w0), "=l"(w1) : "r"(wa));
                asm("ld.shared.v2.u64 {%0,%1}, [%2+16];" : "=l"(w2), "=l"(w3) : "r"(wa));
                asm("ld.shared.v2.u64 {%0,%1}, [%2+32];" : "=l"(w4), "=l"(w5) : "r"(wa));
                asm("ld.shared.v2.u64 {%0,%1}, [%2+48];" : "=l"(w6), "=l"(w7) : "r"(wa));
                asm("fma.rn.f32x2 %0, %1, %2, %0;" : "+l"(acc[0]) : "l"(mm), "l"(w0));
                asm("fma.rn.f32x2 %0, %1, %2, %0;" : "+l"(acc[1]) : "l"(mm), "l"(w1));
                asm("fma.rn.f32x2 %0, %1, %2, %0;" : "+l"(acc[2]) : "l"(mm), "l"(w2));
                asm("fma.rn.f32x2 %0, %1, %2, %0;" : "+l"(acc[3]) : "l"(mm), "l"(w3));
                asm("fma.rn.f32x2 %0, %1, %2, %0;" : "+l"(acc[4]) : "l"(mm), "l"(w4));
                asm("fma.rn.f32x2 %0, %1, %2, %0;" : "+l"(acc[5]) : "l"(mm), "l"(w5));
                asm("fma.rn.f32x2 %0, %1, %2, %0;" : "+l"(acc[6]) : "l"(mm), "l"(w6));
                asm("fma.rn.f32x2 %0, %1, %2, %0;" : "+l"(acc[7]) : "l"(mm), "l"(w7));
            }
        }
        float s = att_b2[0];
        #pragma unroll
        for (int j = 0; j < 8; j++) {
            uint32_t lo_u, hi_u;
            asm("mov.b64 {%0,%1}, %2;" : "=r"(lo_u), "=r"(hi_u) : "l"(acc[j]));
            s += fmaxf(__uint_as_float(lo_u), 0.0f) * w2S[2 * j];
            s += fmaxf(__uint_as_float(hi_u), 0.0f) * w2S[2 * j + 1];
        }
        scoreS[half][lt] = (lt <= len) ? s : -INFINITY;
    }
    __syncthreads();

    // ---- softmax over 50 scores (one full warp per half: warps 0 and 2) ----
    if (lt < 32) {
        float v1 = scoreS[half][lt];
        float v2 = (lt + 32 < M_MEM) ? scoreS[half][lt + 32] : -INFINITY;
        float mx = fmaxf(v1, v2);
        #pragma unroll
        for (int o = 16; o > 0; o >>= 1)
            mx = fmaxf(mx, __shfl_xor_sync(0xffffffffu, mx, o));
        float e1 = __expf(v1 - mx);                   // exp(-inf)=0 handles mask
        float e2 = (lt + 32 < M_MEM) ? __expf(v2 - mx) : 0.0f;
        float sm = e1 + e2;
        #pragma unroll
        for (int o = 16; o > 0; o >>= 1)
            sm += __shfl_xor_sync(0xffffffffu, sm, o);
        float inv = __frcp_rn(sm);
        wtS[half][lt] = e1 * inv;
        if (lt + 32 < M_MEM) wtS[half][lt + 32] = e2 * inv;
    }
    __syncthreads();

    // ---- weighted member sum + group embedding: thread = dim ----
    {
        float g = groupS[half][lt];
        #pragma unroll 10
        for (int m = 0; m < M_MEM; m++)
            g += wtS[half][m] * memS[half][m * PAD + lt];
        gS[half][lt] = g;
    }
    __syncthreads();

    // ---- predict MLP: [g*item, g, item] (192) -> 8 -> 1 ----
    if (lt < 8) {
        float a = pred_b1[lt];
        #pragma unroll 8
        for (int k = 0; k < D_DIM; k++)
            a += (gS[half][k] * itemS[half][k]) * predW[k * 8 + lt];
        #pragma unroll 8
        for (int k = 0; k < D_DIM; k++)
            a += gS[half][k] * predW[(D_DIM + k) * 8 + lt];
        #pragma unroll 8
        for (int k = 0; k < D_DIM; k++)
            a += itemS[half][k] * predW[(2 * D_DIM + k) * 8 + lt];
        float part = fmaxf(a, 0.0f) * pred_w2[lt];
        #pragma unroll
        for (int o = 4; o > 0; o >>= 1)
            part += __shfl_xor_sync(0xffu, part, o);
        if (lt == 0 && valid) {
            float z = part + pred_b2[0];
            out[b] = 1.0f / (1.0f + __expf(-z));
        }
    }
}

extern "C" void kernel_launch(void* const* d_in, const int* in_sizes, int n_in,
                              void* d_out, int out_size)
{
    const int*   group_inputs   = (const int*)  d_in[0];
    const int*   item_inputs    = (const int*)  d_in[1];
    const int*   member_ids     = (const int*)  d_in[2];
    const int*   member_lengths = (const int*)  d_in[3];
    const float* user_table     = (const float*)d_in[4];
    const float* item_table     = (const float*)d_in[5];
    const float* group_table    = (const float*)d_in[6];
    const float* att_w1         = (const float*)d_in[7];
    const float* att_b1         = (const float*)d_in[8];
    const float* att_w2         = (const float*)d_in[9];
    const float* att_b2         = (const float*)d_in[10];
    const float* pred_w1        = (const float*)d_in[11];
    const float* pred_b1        = (const float*)d_in[12];
    const float* pred_w2        = (const float*)d_in[13];
    const float* pred_b2        = (const float*)d_in[14];
    float* out = (float*)d_out;

    int B = in_sizes[0];
    int grid = (B + 1) / 2;
    agree_fused_kernel<<<grid, 128>>>(
        group_inputs, item_inputs, member_ids, member_lengths,
        user_table, item_table, group_table,
        att_w1, att_b1, att_w2, att_b2,
        pred_w1, pred_b1, pred_w2, pred_b2, out, B);
}